// round 11
// baseline (speedup 1.0000x reference)
#include <cuda_runtime.h>
#include <cuda_fp16.h>
#include <cstdint>

// ---------------- problem constants ----------------
#define HDIM   4096
#define MTOT   16384
#define NGRP   8
#define I2     3072
#define IHALF  1536
#define MSPLIT 2048

// ---------------- GEMM tiling ----------------
#define BM      128
#define BN      64              // output cols per CTA (gate AND up computed)
#define KC      64              // fp16 elems per K chunk (128 B rows)
#define NSTAGE  3
#define NITER   (HDIM / KC)     // 64

#define A_BYTES     (BM * KC * 2)              // 16384
#define B_BYTES     (2 * BN * KC * 2)          // 16384 (gate 64 rows + up 64 rows)
#define STAGE_BYTES (A_BYTES + B_BYTES)        // 32768
#define SMEM_BYTES  (NSTAGE * STAGE_BYTES)     // 98304 -> 2 CTAs/SM

// chunking: 4 chunks x 2 groups, single stream; conversion of chunk c+1 is
// appended to the GEMM CTAs of chunk c (fills the partial-wave tail).
#define GPC        2
#define NCHUNK     (NGRP / GPC)                       // 4
#define CTAS_PER_G ((MSPLIT / BM) * (IHALF / BN))     // 384
#define GRID_G     (GPC * CTAS_PER_G)                 // 768
#define X8G        ((MSPLIT * HDIM) / 8)              // 1048576 uint4 per group
#define W8G        ((I2 * HDIM) / 8)                  // 1572864 uint4 per group
#define CHUNK_X    (GPC * X8G)                        // 2097152
#define CHUNK_W    (GPC * W8G)                        // 3145728
#define CHUNK_T    (CHUNK_X + CHUNK_W)                // 5242880

// ---------------- fp16 scratch (device globals; no allocation) ----------------
__device__ __align__(1024) __half g_xh[(size_t)MTOT * HDIM];
__device__ __align__(1024) __half g_wh[(size_t)NGRP * I2 * HDIM];

// ---------------- helpers ----------------
__device__ __forceinline__ uint32_t smem_u32(const void* p) {
    uint32_t a;
    asm("{ .reg .u64 t; cvta.to.shared.u64 t, %1; cvt.u32.u64 %0, t; }" : "=r"(a) : "l"(p));
    return a;
}
__device__ __forceinline__ uint32_t swz(uint32_t o) {
    return o ^ ((o >> 3) & 0x70);
}
__device__ __forceinline__ void cp16(uint32_t s, const void* g) {
    asm volatile("cp.async.cg.shared.global [%0], [%1], 16;" :: "r"(s), "l"(g));
}
__device__ __forceinline__ void cp_commit() {
    asm volatile("cp.async.commit_group;" ::: "memory");
}
template <int N>
__device__ __forceinline__ void cp_wait() {
    asm volatile("cp.async.wait_group %0;" :: "n"(N) : "memory");
}
__device__ __forceinline__ void ldmx4(uint32_t* r, uint32_t addr) {
    asm volatile("ldmatrix.sync.aligned.m8n8.x4.shared.b16 {%0,%1,%2,%3}, [%4];"
                 : "=r"(r[0]), "=r"(r[1]), "=r"(r[2]), "=r"(r[3]) : "r"(addr));
}
__device__ __forceinline__ void mma16816(float* c, const uint32_t* a, const uint32_t* b) {
    asm volatile(
        "mma.sync.aligned.m16n8k16.row.col.f32.f16.f16.f32 "
        "{%0,%1,%2,%3}, {%4,%5,%6,%7}, {%8,%9}, {%0,%1,%2,%3};"
        : "+f"(c[0]), "+f"(c[1]), "+f"(c[2]), "+f"(c[3])
        : "r"(a[0]), "r"(a[1]), "r"(a[2]), "r"(a[3]), "r"(b[0]), "r"(b[1]));
}
__device__ __forceinline__ void stg_cs_f2(float* p, float a, float b) {
    asm volatile("st.global.cs.v2.f32 [%0], {%1,%2};" :: "l"(p), "f"(a), "f"(b) : "memory");
}

// convert one uint4 (8 fp32 -> 8 fp16)
__device__ __forceinline__ void cvt8(const float4* in, uint4* out, size_t j) {
    float4 v0 = __ldcs(in + 2 * j);
    float4 v1 = __ldcs(in + 2 * j + 1);
    __half2 h0 = __floats2half2_rn(v0.x, v0.y);
    __half2 h1 = __floats2half2_rn(v0.z, v0.w);
    __half2 h2 = __floats2half2_rn(v1.x, v1.y);
    __half2 h3 = __floats2half2_rn(v1.z, v1.w);
    uint4 u;
    u.x = *reinterpret_cast<uint32_t*>(&h0);
    u.y = *reinterpret_cast<uint32_t*>(&h1);
    u.z = *reinterpret_cast<uint32_t*>(&h2);
    u.w = *reinterpret_cast<uint32_t*>(&h3);
    __stcs(out + j, u);
}

// ---------------- standalone convert for chunk 0 ----------------
__global__ void cvt_chunk_f16(const float4* __restrict__ x, const float4* __restrict__ w,
                              uint4* __restrict__ xh, uint4* __restrict__ wh, int g0) {
    int i = blockIdx.x * blockDim.x + threadIdx.x;
    if (i < CHUNK_X) cvt8(x, xh, (size_t)g0 * X8G + i);
    else {
        i -= CHUNK_X;
        if (i >= CHUNK_W) return;
        cvt8(w, wh, (size_t)g0 * W8G + i);
    }
}

// ---------------- fused GEMM + SwiGLU + next-chunk convert ----------------
// GEMM for groups [g0, g0+GPC); afterwards each CTA converts a grid-strided
// slice of chunk starting at cvt_g0 (if cvt_g0 >= 0).
__global__ void __launch_bounds__(256, 2)
teswiglu_gemm(const __half* __restrict__ xh, const __half* __restrict__ wh,
              float* __restrict__ out, int g0,
              const float4* __restrict__ xf, const float4* __restrict__ wf,
              uint4* __restrict__ xh4, uint4* __restrict__ wh4, int cvt_g0) {
    extern __shared__ __align__(128) char smem[];
    uint32_t sbase = smem_u32(smem);
    int tid = threadIdx.x;
    int wid = tid >> 5;
    int lid = tid & 31;

    int bid = blockIdx.x;
    int nt = bid % (IHALF / BN);                     // 24
    int mt = (bid / (IHALF / BN)) % (MSPLIT / BM);   // 16
    int g  = g0 + bid / CTAS_PER_G;

    const int m0 = g * MSPLIT + mt * BM;
    const __half* Ag = xh + (size_t)m0 * HDIM;
    const __half* Bg = wh + ((size_t)g * I2 + nt * BN) * HDIM;
    const __half* Bu = Bg + (size_t)IHALF * HDIM;

    auto load_stage = [&](int s, int k0) {
        uint32_t st = sbase + s * STAGE_BYTES;
        #pragma unroll
        for (int c = 0; c < 4; c++) {
            int idx = tid + c * 256;
            int row = idx >> 3, seg = idx & 7;
            cp16(st + swz(row * 128 + seg * 16), Ag + (size_t)row * HDIM + k0 + seg * 8);
        }
        #pragma unroll
        for (int c = 0; c < 4; c++) {
            int idx = tid + c * 256;
            int row = idx >> 3, seg = idx & 7;   // 0..127
            const __half* src = (c < 2) ? (Bg + (size_t)row * HDIM)
                                        : (Bu + (size_t)(row - 64) * HDIM);
            cp16(st + A_BYTES + swz(row * 128 + seg * 16), src + k0 + seg * 8);
        }
        cp_commit();
    };

    #pragma unroll
    for (int s = 0; s < NSTAGE - 1; s++) load_stage(s, s * KC);

    const int wm = wid >> 1;      // 0..3 (32-row slabs)
    const int wn = wid & 1;       // 0..1 (32-col slabs)

    float cg[2][4][4];
    float cu[2][4][4];
    #pragma unroll
    for (int a = 0; a < 2; a++)
        #pragma unroll
        for (int b = 0; b < 4; b++)
            #pragma unroll
            for (int q = 0; q < 4; q++) { cg[a][b][q] = 0.f; cu[a][b][q] = 0.f; }

    const int la_row = (lid & 7) + ((lid >> 3) & 1) * 8;
    const int la_kb  = ((lid >> 4) & 1) * 16;
    const int lb_row = (lid & 7) + ((lid >> 4) & 1) * 8;
    const int lb_kb  = ((lid >> 3) & 1) * 16;

    int cs = 0;
    int ls = NSTAGE - 1;

    for (int it = 0; it < NITER; it++) {
        cp_wait<NSTAGE - 2>();
        __syncthreads();
        int jn = it + NSTAGE - 1;
        if (jn < NITER) {
            load_stage(ls, jn * KC);
            ls = (ls + 1 == NSTAGE) ? 0 : ls + 1;
        }

        uint32_t st = sbase + cs * STAGE_BYTES;
        cs = (cs + 1 == NSTAGE) ? 0 : cs + 1;
        uint32_t sA = st;
        uint32_t sB = st + A_BYTES;

        #pragma unroll
        for (int ki = 0; ki < 4; ki++) {
            uint32_t a[2][4];
            #pragma unroll
            for (int mi = 0; mi < 2; mi++) {
                int row = wm * 32 + mi * 16 + la_row;
                ldmx4(a[mi], sA + swz(row * 128 + ki * 32 + la_kb));
            }
            uint32_t bg[4][2], bu[4][2];
            #pragma unroll
            for (int nj = 0; nj < 2; nj++) {
                int rg = wn * 32 + nj * 16 + lb_row;
                uint32_t t0[4], t1[4];
                ldmx4(t0, sB + swz(rg * 128 + ki * 32 + lb_kb));
                ldmx4(t1, sB + swz((rg + 64) * 128 + ki * 32 + lb_kb));
                bg[2 * nj][0] = t0[0]; bg[2 * nj][1] = t0[1];
                bg[2 * nj + 1][0] = t0[2]; bg[2 * nj + 1][1] = t0[3];
                bu[2 * nj][0] = t1[0]; bu[2 * nj][1] = t1[1];
                bu[2 * nj + 1][0] = t1[2]; bu[2 * nj + 1][1] = t1[3];
            }
            #pragma unroll
            for (int mi = 0; mi < 2; mi++) {
                #pragma unroll
                for (int f = 0; f < 4; f++) {
                    mma16816(cg[mi][f], a[mi], bg[f]);
                    mma16816(cu[mi][f], a[mi], bu[f]);
                }
            }
        }
    }

    // ---- epilogue: silu(gate) * up, streaming fp32 stores ----
    #pragma unroll
    for (int mi = 0; mi < 2; mi++) {
        #pragma unroll
        for (int f = 0; f < 4; f++) {
            int row = m0 + wm * 32 + mi * 16 + (lid >> 2);
            int col = nt * BN + wn * 32 + f * 8 + 2 * (lid & 3);
            float o[4];
            #pragma unroll
            for (int q = 0; q < 4; q++) {
                float gv = cg[mi][f][q];
                float uv = cu[mi][f][q];
                o[q] = gv / (1.0f + __expf(-gv)) * uv;
            }
            stg_cs_f2(out + (size_t)row * IHALF + col, o[0], o[1]);
            stg_cs_f2(out + (size_t)(row + 8) * IHALF + col, o[2], o[3]);
        }
    }

    // ---- tail-fill: convert next chunk's fp32 -> fp16 (grid-strided) ----
    if (cvt_g0 >= 0) {
        for (int i = bid * 256 + tid; i < CHUNK_T; i += GRID_G * 256) {
            if (i < CHUNK_X) cvt8(xf, xh4, (size_t)cvt_g0 * X8G + i);
            else             cvt8(wf, wh4, (size_t)cvt_g0 * W8G + (i - CHUNK_X));
        }
    }
}

// ---------------- host launch: single stream, chunk pipeline ----------------
extern "C" void kernel_launch(void* const* d_in, const int* in_sizes, int n_in,
                              void* d_out, int out_size) {
    const float* x = (const float*)d_in[0];
    const float* w = (const float*)d_in[1];
    float* out = (float*)d_out;

    void* xh_ptr = nullptr;
    void* wh_ptr = nullptr;
    cudaGetSymbolAddress(&xh_ptr, g_xh);
    cudaGetSymbolAddress(&wh_ptr, g_wh);
    const __half* xh = (const __half*)xh_ptr;
    const __half* wh = (const __half*)wh_ptr;

    cudaFuncSetAttribute(teswiglu_gemm, cudaFuncAttributeMaxDynamicSharedMemorySize, SMEM_BYTES);

    // convert chunk 0
    cvt_chunk_f16<<<CHUNK_T / 256, 256>>>((const float4*)x, (const float4*)w,
                                          (uint4*)xh_ptr, (uint4*)wh_ptr, 0);
    // GEMM chunk c + embedded convert of chunk c+1
    for (int c = 0; c < NCHUNK; c++) {
        int cvt_g0 = (c + 1 < NCHUNK) ? (c + 1) * GPC : -1;
        teswiglu_gemm<<<GRID_G, 256, SMEM_BYTES>>>(
            xh, wh, out, c * GPC,
            (const float4*)x, (const float4*)w,
            (uint4*)xh_ptr, (uint4*)wh_ptr, cvt_g0);
    }
}

// round 14
// speedup vs baseline: 1.1487x; 1.1487x over previous
#include <cuda_runtime.h>
#include <cuda_fp16.h>
#include <cstdint>

// ---------------- problem constants ----------------
#define HDIM   4096
#define MTOT   16384
#define NGRP   8
#define I2     3072
#define IHALF  1536
#define MSPLIT 2048

// ---------------- GEMM tiling ----------------
#define BM      128
#define BN      64              // output cols per CTA (gate AND up computed)
#define KC      64              // fp16 elems per K chunk (128 B rows)
#define NSTAGE  3
#define NITER   (HDIM / KC)     // 64

#define A_BYTES     (BM * KC * 2)              // 16384
#define B_BYTES     (2 * BN * KC * 2)          // 16384 (gate 64 rows + up 64 rows)
#define STAGE_BYTES (A_BYTES + B_BYTES)        // 32768

// SMEM: [0:24) full mbarriers, [24:48) empty mbarriers, stages at 1024
#define OFF_FULL   0
#define OFF_EMPTY  24
#define OFF_TILES  1024
#define SMEM_BYTES (OFF_TILES + NSTAGE * STAGE_BYTES)   // 99328 -> 2 CTAs/SM

// ---------------- fp16 scratch (device globals; no allocation) ----------------
__device__ __align__(1024) __half g_xh[(size_t)MTOT * HDIM];
__device__ __align__(1024) __half g_wh[(size_t)NGRP * I2 * HDIM];

#define N8X ((MTOT * HDIM) / 8)
#define N8W ((NGRP * I2 * HDIM) / 8)

// ---------------- helpers ----------------
__device__ __forceinline__ uint32_t smem_u32(const void* p) {
    uint32_t a;
    asm("{ .reg .u64 t; cvta.to.shared.u64 t, %1; cvt.u32.u64 %0, t; }" : "=r"(a) : "l"(p));
    return a;
}
__device__ __forceinline__ uint32_t swz(uint32_t o) {
    return o ^ ((o >> 3) & 0x70);
}
__device__ __forceinline__ void cp16(uint32_t s, const void* g) {
    asm volatile("cp.async.cg.shared.global [%0], [%1], 16;" :: "r"(s), "l"(g));
}
#define MBARRIER_INIT(addr, cnt) \
    asm volatile("mbarrier.init.shared.b64 [%0], %1;" :: "r"(addr), "r"(cnt) : "memory")
#define MBARRIER_ARRIVE(addr) \
    asm volatile("mbarrier.arrive.shared.b64 _, [%0];" :: "r"(addr) : "memory")
// NOINC is load-bearing: the default variant increments the pending count at
// issue (expect-tx-like) and the barrier with init count 256 would never flip.
#define CPASYNC_MBAR_ARRIVE_NOINC(addr) \
    asm volatile("cp.async.mbarrier.arrive.noinc.shared.b64 [%0];" :: "r"(addr) : "memory")
__device__ __forceinline__ void mbar_wait(uint32_t mbar, uint32_t parity) {
    asm volatile(
        "{\n\t.reg .pred P;\n\t"
        "W_%=:\n\t"
        "mbarrier.try_wait.parity.acquire.cta.shared::cta.b64 P, [%0], %1, 0x989680;\n\t"
        "@!P bra W_%=;\n\t}"
        :: "r"(mbar), "r"(parity) : "memory");
}
__device__ __forceinline__ void ldmx4(uint32_t* r, uint32_t addr) {
    asm volatile("ldmatrix.sync.aligned.m8n8.x4.shared.b16 {%0,%1,%2,%3}, [%4];"
                 : "=r"(r[0]), "=r"(r[1]), "=r"(r[2]), "=r"(r[3]) : "r"(addr));
}
__device__ __forceinline__ void mma16816(float* c, const uint32_t* a, const uint32_t* b) {
    asm volatile(
        "mma.sync.aligned.m16n8k16.row.col.f32.f16.f16.f32 "
        "{%0,%1,%2,%3}, {%4,%5,%6,%7}, {%8,%9}, {%0,%1,%2,%3};"
        : "+f"(c[0]), "+f"(c[1]), "+f"(c[2]), "+f"(c[3])
        : "r"(a[0]), "r"(a[1]), "r"(a[2]), "r"(a[3]), "r"(b[0]), "r"(b[1]));
}
__device__ __forceinline__ void stg_cs_f2(float* p, float a, float b) {
    asm volatile("st.global.cs.v2.f32 [%0], {%1,%2};" :: "l"(p), "f"(a), "f"(b) : "memory");
}

// ---------------- fp32 -> fp16 convert (x and w, streaming, 8 elems/thread) ----------------
__global__ void cvt_all_f16(const float4* __restrict__ x, const float4* __restrict__ w,
                            uint4* __restrict__ xh, uint4* __restrict__ wh) {
    int i = blockIdx.x * blockDim.x + threadIdx.x;
    const float4* in;
    uint4* out;
    int j;
    if (i < N8X) { in = x; out = xh; j = i; }
    else         { in = w; out = wh; j = i - N8X; if (j >= N8W) return; }
    float4 v0 = __ldcs(in + 2 * (size_t)j);
    float4 v1 = __ldcs(in + 2 * (size_t)j + 1);
    __half2 h0 = __floats2half2_rn(v0.x, v0.y);
    __half2 h1 = __floats2half2_rn(v0.z, v0.w);
    __half2 h2 = __floats2half2_rn(v1.x, v1.y);
    __half2 h3 = __floats2half2_rn(v1.z, v1.w);
    uint4 u;
    u.x = *reinterpret_cast<uint32_t*>(&h0);
    u.y = *reinterpret_cast<uint32_t*>(&h1);
    u.z = *reinterpret_cast<uint32_t*>(&h2);
    u.w = *reinterpret_cast<uint32_t*>(&h3);
    __stcs(out + j, u);
}

// ---------------- fused GEMM + SwiGLU (2 CTAs/SM, mbarrier pipeline) ----------------
// CTA tile: 128 rows x 64 output cols (gate + up both computed).
// 8 warps: wm = wid>>1 (4 x 32 rows), wn = wid&1 (2 x 32 cols).
// No __syncthreads in the mainloop: full[s] signaled by
// cp.async.mbarrier.arrive.noinc (count 256), empty[s] by one arrive per warp
// (count 8). Warps skew freely within the 3-stage ring.
__global__ void __launch_bounds__(256, 2)
teswiglu_gemm(const __half* __restrict__ xh, const __half* __restrict__ wh,
              float* __restrict__ out) {
    extern __shared__ __align__(1024) char smem[];
    uint32_t sbase = smem_u32(smem);
    int tid = threadIdx.x;
    int wid = tid >> 5;
    int lid = tid & 31;

    int bid = blockIdx.x;
    int nt = bid % (IHALF / BN);                     // 24
    int mt = (bid / (IHALF / BN)) % (MSPLIT / BM);   // 16
    int g  = bid / ((IHALF / BN) * (MSPLIT / BM));

    const int m0 = g * MSPLIT + mt * BM;
    const __half* Ag = xh + (size_t)m0 * HDIM;
    const __half* Bg = wh + ((size_t)g * I2 + nt * BN) * HDIM;
    const __half* Bu = Bg + (size_t)IHALF * HDIM;

    if (tid == 0) {
        #pragma unroll
        for (int s = 0; s < NSTAGE; s++) {
            MBARRIER_INIT(sbase + OFF_FULL + s * 8, 256);
            MBARRIER_INIT(sbase + OFF_EMPTY + s * 8, 8);
        }
    }
    __syncthreads();

    // one stage: A 128 rows + B 128 rows (gate 0-63, up 64-127); ends with
    // cp.async.mbarrier.arrive.noinc on full[s].
    auto load_stage = [&](int s, int k0) {
        uint32_t st = sbase + OFF_TILES + s * STAGE_BYTES;
        #pragma unroll
        for (int c = 0; c < 4; c++) {
            int idx = tid + c * 256;
            int row = idx >> 3, seg = idx & 7;
            cp16(st + swz(row * 128 + seg * 16), Ag + (size_t)row * HDIM + k0 + seg * 8);
        }
        #pragma unroll
        for (int c = 0; c < 4; c++) {
            int idx = tid + c * 256;
            int row = idx >> 3, seg = idx & 7;   // 0..127
            const __half* src = (c < 2) ? (Bg + (size_t)row * HDIM)
                                        : (Bu + (size_t)(row - 64) * HDIM);
            cp16(st + A_BYTES + swz(row * 128 + seg * 16), src + k0 + seg * 8);
        }
        CPASYNC_MBAR_ARRIVE_NOINC(sbase + OFF_FULL + s * 8);
    };

    // prologue: fill stages 0..NSTAGE-2
    #pragma unroll
    for (int s = 0; s < NSTAGE - 1; s++) load_stage(s, s * KC);

    const int wm = wid >> 1;      // 0..3 (32-row slabs)
    const int wn = wid & 1;       // 0..1 (32-col slabs)

    float cg[2][4][4];
    float cu[2][4][4];
    #pragma unroll
    for (int a = 0; a < 2; a++)
        #pragma unroll
        for (int b = 0; b < 4; b++)
            #pragma unroll
            for (int q = 0; q < 4; q++) { cg[a][b][q] = 0.f; cu[a][b][q] = 0.f; }

    const int la_row = (lid & 7) + ((lid >> 3) & 1) * 8;
    const int la_kb  = ((lid >> 4) & 1) * 16;
    const int lb_row = (lid & 7) + ((lid >> 4) & 1) * 8;
    const int lb_kb  = ((lid >> 3) & 1) * 16;

    int cs = 0, pc = 0;            // consumer cursor (stage, phase)
    int ls = NSTAGE - 1, pl = 1;   // producer cursor; phase 1 -> first empty-waits pass

    for (int it = 0; it < NITER; it++) {
        mbar_wait(sbase + OFF_FULL + cs * 8, (uint32_t)pc);

        uint32_t st = sbase + OFF_TILES + cs * STAGE_BYTES;
        uint32_t sA = st;
        uint32_t sB = st + A_BYTES;

        #pragma unroll
        for (int ki = 0; ki < 4; ki++) {
            uint32_t a[2][4];
            #pragma unroll
            for (int mi = 0; mi < 2; mi++) {
                int row = wm * 32 + mi * 16 + la_row;
                ldmx4(a[mi], sA + swz(row * 128 + ki * 32 + la_kb));
            }
            uint32_t bg[4][2], bu[4][2];
            #pragma unroll
            for (int nj = 0; nj < 2; nj++) {
                int rg = wn * 32 + nj * 16 + lb_row;
                uint32_t t0[4], t1[4];
                ldmx4(t0, sB + swz(rg * 128 + ki * 32 + lb_kb));
                ldmx4(t1, sB + swz((rg + 64) * 128 + ki * 32 + lb_kb));
                bg[2 * nj][0] = t0[0]; bg[2 * nj][1] = t0[1];
                bg[2 * nj + 1][0] = t0[2]; bg[2 * nj + 1][1] = t0[3];
                bu[2 * nj][0] = t1[0]; bu[2 * nj][1] = t1[1];
                bu[2 * nj + 1][0] = t1[2]; bu[2 * nj + 1][1] = t1[3];
            }
            #pragma unroll
            for (int mi = 0; mi < 2; mi++) {
                #pragma unroll
                for (int f = 0; f < 4; f++) {
                    mma16816(cg[mi][f], a[mi], bg[f]);
                    mma16816(cu[mi][f], a[mi], bu[f]);
                }
            }
        }

        __syncwarp();
        if (lid == 0) MBARRIER_ARRIVE(sbase + OFF_EMPTY + cs * 8);
        if (++cs == NSTAGE) { cs = 0; pc ^= 1; }

        int jn = it + NSTAGE - 1;
        if (jn < NITER) {
            mbar_wait(sbase + OFF_EMPTY + ls * 8, (uint32_t)pl);
            load_stage(ls, jn * KC);
            if (++ls == NSTAGE) { ls = 0; pl ^= 1; }
        }
    }

    // ---- epilogue: silu(gate) * up, streaming fp32 stores ----
    #pragma unroll
    for (int mi = 0; mi < 2; mi++) {
        #pragma unroll
        for (int f = 0; f < 4; f++) {
            int row = m0 + wm * 32 + mi * 16 + (lid >> 2);
            int col = nt * BN + wn * 32 + f * 8 + 2 * (lid & 3);
            float o[4];
            #pragma unroll
            for (int q = 0; q < 4; q++) {
                float gv = cg[mi][f][q];
                float uv = cu[mi][f][q];
                o[q] = gv / (1.0f + __expf(-gv)) * uv;
            }
            stg_cs_f2(out + (size_t)row * IHALF + col, o[0], o[1]);
            stg_cs_f2(out + (size_t)(row + 8) * IHALF + col, o[2], o[3]);
        }
    }
}

// ---------------- host launch ----------------
extern "C" void kernel_launch(void* const* d_in, const int* in_sizes, int n_in,
                              void* d_out, int out_size) {
    const float* x = (const float*)d_in[0];
    const float* w = (const float*)d_in[1];
    float* out = (float*)d_out;

    void* xh_ptr = nullptr;
    void* wh_ptr = nullptr;
    cudaGetSymbolAddress(&xh_ptr, g_xh);
    cudaGetSymbolAddress(&wh_ptr, g_wh);

    {
        int n8 = N8X + N8W;
        cvt_all_f16<<<n8 / 256, 256>>>((const float4*)x, (const float4*)w,
                                       (uint4*)xh_ptr, (uint4*)wh_ptr);
    }

    cudaFuncSetAttribute(teswiglu_gemm, cudaFuncAttributeMaxDynamicSharedMemorySize, SMEM_BYTES);
    int grid = NGRP * (MSPLIT / BM) * (IHALF / BN);  // 3072
    teswiglu_gemm<<<grid, 256, SMEM_BYTES>>>((const __half*)xh_ptr, (const __half*)wh_ptr, out);
}